// round 2
// baseline (speedup 1.0000x reference)
#include <cuda_runtime.h>
#include <math.h>

// Fixed shapes
#define N_BATCH   64
#define C_IN      4
#define T_IN      300
#define V_IN      17
#define M_PERS    10
#define CF        256
#define TF        75
#define NUM_CLASS 60
#define KNN       4
#define LAMBDA_FUSE 0.1f
#define HIP_L 11

#define TV_COUNT (TF * V_IN)          // 1275
#define SLAB_F   (TV_COUNT * M_PERS)  // 12750 floats per (n,c)
#define PAIR_F   (2 * SLAB_F)         // 25500 floats per slab pair (float4-aligned)
#define PAIR_F4  (PAIR_F / 4)         // 6375 float4 per pair
#define STRADDLE 3187                 // float4 index straddling the c boundary

// Scratch (device globals: allocation-free)
__device__ float g_pf[N_BATCH * M_PERS * CF];   // pf[n][m][c]

// ----------------------------------------------------------------------------
// Kernel 1: pf[n][m][c] = mean over (t,v) of feat[n][c][t][v][m]
// One block per slab PAIR (n, 2 channels). 320 threads, float4 loads.
// 320 % 5 == 0 -> each thread's m-phase (4q mod 10) is constant, so its 4
// float4 lanes always hit the same 4 m-buckets (mod 10).
// ----------------------------------------------------------------------------
__global__ __launch_bounds__(320) void k_pf_reduce(const float* __restrict__ feat) {
    const int b   = blockIdx.x;          // pair index: n*128 + cpair
    const int n   = b >> 7;
    const int c0  = (b & 127) * 2;
    const int tid = threadIdx.x;

    const float4* __restrict__ slab =
        reinterpret_cast<const float4*>(feat + (size_t)b * PAIR_F);

    float a0 = 0.f, a1 = 0.f, a2 = 0.f, a3 = 0.f;   // channel c0, lane slots 0..3
    float d0 = 0.f, d1 = 0.f, d2 = 0.f, d3 = 0.f;   // channel c0+1
#pragma unroll
    for (int k = 0; k < 20; k++) {
        int q = tid + 320 * k;
        if (q < PAIR_F4) {
            float4 v = slab[q];
            if (q < STRADDLE)      { a0 += v.x; a1 += v.y; a2 += v.z; a3 += v.w; }
            else if (q > STRADDLE) { d0 += v.x; d1 += v.y; d2 += v.z; d3 += v.w; }
            else                   { a0 += v.x; a1 += v.y; d2 += v.z; d3 += v.w; }
        }
    }

    __shared__ float sm[8][320];
    sm[0][tid] = a0; sm[1][tid] = a1; sm[2][tid] = a2; sm[3][tid] = a3;
    sm[4][tid] = d0; sm[5][tid] = d1; sm[6][tid] = d2; sm[7][tid] = d3;
    __syncthreads();

    // 20 outputs: (cc in {0,1}) x (m in 0..9). For target m, the two
    // contributing (r = tid%5, lane) pairs satisfy (4r + lane) % 10 == m:
    //   pair1: r = m/4,      lane = m%4
    //   pair2: r = (m+10)/4, lane = (m+10)%4
    if (tid < 20) {
        const int cc = tid / 10;
        const int m  = tid % 10;
        const int r1 = m >> 2,        l1 = m & 3;
        const int r2 = (m + 10) >> 2, l2 = (m + 10) & 3;
        const float* p1 = sm[cc * 4 + l1];
        const float* p2 = sm[cc * 4 + l2];
        float acc = 0.f;
#pragma unroll
        for (int g = 0; g < 64; g++) acc += p1[g * 5 + r1] + p2[g * 5 + r2];
        g_pf[(size_t)n * (M_PERS * CF) + m * CF + (c0 + cc)] =
            acc * (1.0f / (float)TV_COUNT);
    }
}

// ----------------------------------------------------------------------------
// Kernel 2 (fused head): one block per n, 512 threads.
//   pos   = mean_t 0.5*(x[:,0:3,:,11,:] + x[:,0:3,:,12,:])   (done in-block)
//   h     = pf @ Wp^T + bp
//   A     = row-normalized kNN adjacency (+self loop)
//   h     = relu(h + 0.1 * A h);  hbar = mean_m h
//   out   = logits_base + sigmoid(tag_scale) * (hbar @ Wc^T + bc)
// ----------------------------------------------------------------------------
__global__ __launch_bounds__(512) void k_head(
    const float* __restrict__ x,
    const float* __restrict__ logits_base,
    const float* __restrict__ proj_w, const float* __restrict__ proj_b,
    const float* __restrict__ cls_w,  const float* __restrict__ cls_b,
    const float* __restrict__ tag_scale,
    float* __restrict__ out)
{
    const int n   = blockIdx.x;
    const int tid = threadIdx.x;

    __shared__ float s_pf[M_PERS][CF];
    __shared__ float s_h [M_PERS][CF];
    __shared__ float s_posred[480];
    __shared__ float s_pos[M_PERS][3];
    __shared__ float s_d [M_PERS][M_PERS];
    __shared__ float s_A [M_PERS][M_PERS];
    __shared__ float s_hb[2][CF];
    __shared__ float s_hbar[CF];
    __shared__ float s_cred[NUM_CLASS][8];

    // ---- stage 0a: pos partial sums (480 threads) ----
    // layout: c = tid/160, tg = (tid%160)/20, j = tid%20
    //   j<10 : v=HIP_L, m=j ; j>=10 : v=HIP_L+1, m=j-10
    if (tid < 480) {
        const int c  = tid / 160;
        const int rm = tid % 160;
        const int tg = rm / 20;
        const int j  = rm % 20;
        const float* base = x + ((size_t)(n * C_IN + c) * T_IN) * (V_IN * M_PERS)
                              + HIP_L * M_PERS + j;
        float s = 0.f;
#pragma unroll
        for (int k = 0; k < 38; k++) {
            int t = tg + 8 * k;
            if (t < T_IN) s += base[(size_t)t * (V_IN * M_PERS)];
        }
        s_posred[tid] = s;
    }

    // ---- stage 0b: load pf slab (float4) ----
    {
        const float4* src = reinterpret_cast<const float4*>(
            g_pf + (size_t)n * (M_PERS * CF));
        float4* dst = reinterpret_cast<float4*>(&s_pf[0][0]);
#pragma unroll
        for (int i = tid; i < (M_PERS * CF) / 4; i += 512) dst[i] = src[i];
    }
    __syncthreads();

    // ---- proj GEMM: tid = (half, c); each thread does 5 persons ----
    const int c    = tid & 255;
    const int half = tid >> 8;
    {
        const float4* wrow = reinterpret_cast<const float4*>(proj_w + (size_t)c * CF);
        float acc[5] = {0.f, 0.f, 0.f, 0.f, 0.f};
#pragma unroll 4
        for (int kq = 0; kq < CF / 4; kq++) {
            float4 w4 = wrow[kq];
#pragma unroll
            for (int mm = 0; mm < 5; mm++) {
                const int m = half * 5 + mm;
                float4 p = *reinterpret_cast<const float4*>(&s_pf[m][kq * 4]);
                acc[mm] += p.x * w4.x + p.y * w4.y + p.z * w4.z + p.w * w4.w;
            }
        }
        const float bc = proj_b[c];
#pragma unroll
        for (int mm = 0; mm < 5; mm++) s_h[half * 5 + mm][c] = acc[mm] + bc;
    }

    // ---- stage 0c: finish pos reduction (30 threads; independent smem) ----
    if (tid < 30) {
        const int cc = tid / 10;
        const int m  = tid % 10;
        float sL = 0.f, sR = 0.f;
#pragma unroll
        for (int tg = 0; tg < 8; tg++) {
            sL += s_posred[cc * 160 + tg * 20 + m];
            sR += s_posred[cc * 160 + tg * 20 + m + 10];
        }
        s_pos[m][cc] = (sL + sR) * 0.5f * (1.0f / (float)T_IN);
    }
    __syncthreads();

    // ---- pairwise distances ----
    if (tid < M_PERS * M_PERS) {
        const int i = tid / M_PERS, j = tid % M_PERS;
        float dx = s_pos[i][0] - s_pos[j][0];
        float dy = s_pos[i][1] - s_pos[j][1];
        float dz = s_pos[i][2] - s_pos[j][2];
        s_d[i][j] = sqrtf(dx * dx + dy * dy + dz * dz);
    }
    __syncthreads();

    // ---- top-k (k=4 smallest, lowest-index tiebreak like lax.top_k) ----
    if (tid < M_PERS) {
        const int i = tid;
        float a[M_PERS];
        bool sel[M_PERS];
#pragma unroll
        for (int j = 0; j < M_PERS; j++) { a[j] = 0.f; sel[j] = false; }
#pragma unroll
        for (int s = 0; s < KNN; s++) {
            int   arg  = -1;
            float best = 3.4e38f;
#pragma unroll
            for (int j = 0; j < M_PERS; j++)
                if (!sel[j] && s_d[i][j] < best) { best = s_d[i][j]; arg = j; }
            sel[arg] = true;
            a[arg] = 1.f;
        }
        a[i] += 1.f;                      // self loop
        float rs = 0.f;
#pragma unroll
        for (int j = 0; j < M_PERS; j++) rs += a[j];
        float inv = 1.0f / (rs + 1e-6f);
#pragma unroll
        for (int j = 0; j < M_PERS; j++) s_A[i][j] = a[j] * inv;
    }
    __syncthreads();

    // ---- fuse + relu + partial mean over this half's 5 persons ----
    {
        float hb = 0.f;
#pragma unroll
        for (int mm = 0; mm < 5; mm++) {
            const int m = half * 5 + mm;
            float g = 0.f;
#pragma unroll
            for (int p = 0; p < M_PERS; p++) g += s_A[m][p] * s_h[p][c];
            float hf = s_h[m][c] + LAMBDA_FUSE * g;
            hb += fmaxf(hf, 0.f);
        }
        s_hb[half][c] = hb;
    }
    __syncthreads();

    if (tid < CF) s_hbar[tid] = (s_hb[0][tid] + s_hb[1][tid]) * (1.0f / (float)M_PERS);
    __syncthreads();

    // ---- classifier: 480 threads, 8 partials per class ----
    if (tid < NUM_CLASS * 8) {
        const int o    = tid >> 3;
        const int part = tid & 7;
        const float4* wr =
            reinterpret_cast<const float4*>(cls_w + (size_t)o * CF + part * 32);
        float dot = 0.f;
#pragma unroll
        for (int kq = 0; kq < 8; kq++) {
            float4 w4 = wr[kq];
            const int k = part * 32 + kq * 4;
            dot += s_hbar[k]     * w4.x + s_hbar[k + 1] * w4.y
                 + s_hbar[k + 2] * w4.z + s_hbar[k + 3] * w4.w;
        }
        s_cred[o][part] = dot;
    }
    __syncthreads();

    if (tid < NUM_CLASS) {
        float dot = 0.f;
#pragma unroll
        for (int p = 0; p < 8; p++) dot += s_cred[tid][p];
        float lt   = dot + cls_b[tid];
        float gate = 1.0f / (1.0f + expf(-tag_scale[0]));  // *TAG_SCALE_MAX*RAMP = *1
        out[n * NUM_CLASS + tid] = logits_base[n * NUM_CLASS + tid] + gate * lt;
    }
}

// ----------------------------------------------------------------------------
// Launch
// ----------------------------------------------------------------------------
extern "C" void kernel_launch(void* const* d_in, const int* in_sizes, int n_in,
                              void* d_out, int out_size) {
    const float* x           = (const float*)d_in[0];
    const float* feat        = (const float*)d_in[1];
    const float* logits_base = (const float*)d_in[2];
    const float* proj_w      = (const float*)d_in[3];
    const float* proj_b      = (const float*)d_in[4];
    const float* cls_w       = (const float*)d_in[5];
    const float* cls_b       = (const float*)d_in[6];
    const float* tag_scale   = (const float*)d_in[7];
    float* out = (float*)d_out;

    k_pf_reduce<<<(N_BATCH * CF) / 2, 320>>>(feat);
    k_head<<<N_BATCH, 512>>>(x, logits_base, proj_w, proj_b, cls_w, cls_b,
                             tag_scale, out);
}

// round 3
// speedup vs baseline: 1.0395x; 1.0395x over previous
#include <cuda_runtime.h>
#include <math.h>

// Fixed shapes
#define N_BATCH   64
#define C_IN      4
#define T_IN      300
#define V_IN      17
#define M_PERS    10
#define CF        256
#define TF        75
#define NUM_CLASS 60
#define KNN       4
#define LAMBDA_FUSE 0.1f
#define HIP_L 11

#define TV_COUNT (TF * V_IN)          // 1275
#define SLAB_F   (TV_COUNT * M_PERS)  // 12750 floats per (n,c)
#define PAIR_F   (2 * SLAB_F)         // 25500 floats per pair (float4-aligned)
#define PAIR_F4  (PAIR_F / 4)         // 6375 float4 per pair
#define STRADDLE 3187                 // float4 straddling the c boundary

#define N_PF_BLOCKS  ((N_BATCH * CF) / 2)   // 8192
#define N_POS_BLOCKS (N_BATCH * 3)          // 192

// Scratch (device globals: allocation-free)
__device__ float g_pf [N_BATCH * M_PERS * CF];  // pf[n][m][c]
__device__ float g_pos[N_BATCH * M_PERS * 3];   // pos[n][m][xyz]

// ----------------------------------------------------------------------------
// Kernel 1 (combined): blocks [0,8192) reduce feat -> g_pf (slab pairs,
// float4, streaming). Blocks [8192, 8384) reduce x hip rows -> g_pos.
// The pos blocks hide entirely inside the DRAM-bound pf wave.
// ----------------------------------------------------------------------------
__global__ __launch_bounds__(320) void k_reduce(const float* __restrict__ feat,
                                                const float* __restrict__ x) {
    const int tid = threadIdx.x;
    __shared__ float sm[8][320];

    if (blockIdx.x < N_PF_BLOCKS) {
        // ---------------- pf pair reduction ----------------
        const int b  = blockIdx.x;           // n*128 + cpair
        const int n  = b >> 7;
        const int c0 = (b & 127) * 2;

        const float4* __restrict__ slab =
            reinterpret_cast<const float4*>(feat + (size_t)b * PAIR_F);

        float a0 = 0.f, a1 = 0.f, a2 = 0.f, a3 = 0.f;  // channel c0
        float d0 = 0.f, d1 = 0.f, d2 = 0.f, d3 = 0.f;  // channel c0+1
#pragma unroll
        for (int k = 0; k < 20; k++) {
            int q = tid + 320 * k;
            if (q < PAIR_F4) {
                float4 v = __ldcs(&slab[q]);           // streaming: no reuse
                if (q < STRADDLE)      { a0 += v.x; a1 += v.y; a2 += v.z; a3 += v.w; }
                else if (q > STRADDLE) { d0 += v.x; d1 += v.y; d2 += v.z; d3 += v.w; }
                else                   { a0 += v.x; a1 += v.y; d2 += v.z; d3 += v.w; }
            }
        }

        sm[0][tid] = a0; sm[1][tid] = a1; sm[2][tid] = a2; sm[3][tid] = a3;
        sm[4][tid] = d0; sm[5][tid] = d1; sm[6][tid] = d2; sm[7][tid] = d3;
        __syncthreads();

        // 20 outputs: (cc in {0,1}) x (m in 0..9). (4r + lane) % 10 == m:
        //   pair1: r=m/4, lane=m%4 ; pair2: r=(m+10)/4, lane=(m+10)%4
        if (tid < 20) {
            const int cc = tid / 10;
            const int m  = tid % 10;
            const int r1 = m >> 2,        l1 = m & 3;
            const int r2 = (m + 10) >> 2, l2 = (m + 10) & 3;
            const float* p1 = sm[cc * 4 + l1];
            const float* p2 = sm[cc * 4 + l2];
            float acc = 0.f;
#pragma unroll
            for (int g = 0; g < 64; g++) acc += p1[g * 5 + r1] + p2[g * 5 + r2];
            g_pf[(size_t)n * (M_PERS * CF) + m * CF + (c0 + cc)] =
                acc * (1.0f / (float)TV_COUNT);
        }
    } else {
        // ---------------- pos reduction ----------------
        const int bb = blockIdx.x - N_PF_BLOCKS;  // n*3 + c
        const int n  = bb / 3;
        const int c  = bb % 3;
        const int j  = tid % 20;   // j<10: v=HIP_L,m=j ; j>=10: v=HIP_L+1,m=j-10
        const int tg = tid / 20;   // 0..15

        const float* base = x + ((size_t)(n * C_IN + c) * T_IN) * (V_IN * M_PERS)
                              + HIP_L * M_PERS + j;
        float s = 0.f;
#pragma unroll
        for (int k = 0; k < 19; k++) {
            int t = tg + 16 * k;
            if (t < T_IN) s += __ldcs(&base[(size_t)t * (V_IN * M_PERS)]);
        }

        sm[0][tid] = s;
        __syncthreads();

        if (tid < 20) {
            float acc = 0.f;
#pragma unroll
            for (int g = 0; g < 16; g++) acc += sm[0][g * 20 + tid];
            sm[1][tid] = acc;
        }
        __syncthreads();

        if (tid < M_PERS) {
            float v = (sm[1][tid] + sm[1][tid + 10]) * 0.5f * (1.0f / (float)T_IN);
            g_pos[n * (M_PERS * 3) + tid * 3 + c] = v;
        }
    }
}

// ----------------------------------------------------------------------------
// Kernel 2: head. One block per n, 512 threads. Pure on-chip after tiny loads.
// ----------------------------------------------------------------------------
__global__ __launch_bounds__(512) void k_head(
    const float* __restrict__ logits_base,
    const float* __restrict__ proj_w, const float* __restrict__ proj_b,
    const float* __restrict__ cls_w,  const float* __restrict__ cls_b,
    const float* __restrict__ tag_scale,
    float* __restrict__ out)
{
    const int n   = blockIdx.x;
    const int tid = threadIdx.x;

    __shared__ float s_pf[M_PERS][CF];
    __shared__ float s_h [M_PERS][CF];
    __shared__ float s_pos[M_PERS][3];
    __shared__ float s_d [M_PERS][M_PERS];
    __shared__ float s_A [M_PERS][M_PERS];
    __shared__ float s_hb[2][CF];
    __shared__ float s_hbar[CF];
    __shared__ float s_cred[NUM_CLASS][8];

    // ---- tiny loads ----
    {
        const float4* src = reinterpret_cast<const float4*>(
            g_pf + (size_t)n * (M_PERS * CF));
        float4* dst = reinterpret_cast<float4*>(&s_pf[0][0]);
#pragma unroll
        for (int i = tid; i < (M_PERS * CF) / 4; i += 512) dst[i] = src[i];
    }
    if (tid < M_PERS * 3) {
        s_pos[tid / 3][tid % 3] = g_pos[n * (M_PERS * 3) + tid];
    }
    __syncthreads();

    // ---- pairwise distances (runs before GEMM; needs only s_pos) ----
    if (tid >= 256 && tid < 256 + M_PERS * M_PERS) {
        const int q = tid - 256;
        const int i = q / M_PERS, j = q % M_PERS;
        float dx = s_pos[i][0] - s_pos[j][0];
        float dy = s_pos[i][1] - s_pos[j][1];
        float dz = s_pos[i][2] - s_pos[j][2];
        s_d[i][j] = sqrtf(dx * dx + dy * dy + dz * dz);
    }

    // ---- proj GEMM: tid = (half, c); each thread does 5 persons ----
    const int c    = tid & 255;
    const int half = tid >> 8;
    {
        const float4* wrow = reinterpret_cast<const float4*>(proj_w + (size_t)c * CF);
        float acc[5] = {0.f, 0.f, 0.f, 0.f, 0.f};
#pragma unroll 4
        for (int kq = 0; kq < CF / 4; kq++) {
            float4 w4 = wrow[kq];
#pragma unroll
            for (int mm = 0; mm < 5; mm++) {
                const int m = half * 5 + mm;
                float4 p = *reinterpret_cast<const float4*>(&s_pf[m][kq * 4]);
                acc[mm] += p.x * w4.x + p.y * w4.y + p.z * w4.z + p.w * w4.w;
            }
        }
        const float bc = proj_b[c];
#pragma unroll
        for (int mm = 0; mm < 5; mm++) s_h[half * 5 + mm][c] = acc[mm] + bc;
    }
    __syncthreads();

    // ---- top-k (k=4 smallest, lowest-index tiebreak like lax.top_k) ----
    if (tid < M_PERS) {
        const int i = tid;
        float a[M_PERS];
        bool sel[M_PERS];
#pragma unroll
        for (int j = 0; j < M_PERS; j++) { a[j] = 0.f; sel[j] = false; }
#pragma unroll
        for (int s = 0; s < KNN; s++) {
            int   arg  = -1;
            float best = 3.4e38f;
#pragma unroll
            for (int j = 0; j < M_PERS; j++)
                if (!sel[j] && s_d[i][j] < best) { best = s_d[i][j]; arg = j; }
            sel[arg] = true;
            a[arg] = 1.f;
        }
        a[i] += 1.f;                      // self loop
        float rs = 0.f;
#pragma unroll
        for (int j = 0; j < M_PERS; j++) rs += a[j];
        float inv = 1.0f / (rs + 1e-6f);
#pragma unroll
        for (int j = 0; j < M_PERS; j++) s_A[i][j] = a[j] * inv;
    }
    __syncthreads();

    // ---- fuse + relu + partial mean over this half's 5 persons ----
    {
        float hb = 0.f;
#pragma unroll
        for (int mm = 0; mm < 5; mm++) {
            const int m = half * 5 + mm;
            float g = 0.f;
#pragma unroll
            for (int p = 0; p < M_PERS; p++) g += s_A[m][p] * s_h[p][c];
            float hf = s_h[m][c] + LAMBDA_FUSE * g;
            hb += fmaxf(hf, 0.f);
        }
        s_hb[half][c] = hb;
    }
    __syncthreads();

    if (tid < CF) s_hbar[tid] = (s_hb[0][tid] + s_hb[1][tid]) * (1.0f / (float)M_PERS);
    __syncthreads();

    // ---- classifier: 480 threads, 8 partials per class ----
    if (tid < NUM_CLASS * 8) {
        const int o    = tid >> 3;
        const int part = tid & 7;
        const float4* wr =
            reinterpret_cast<const float4*>(cls_w + (size_t)o * CF + part * 32);
        float dot = 0.f;
#pragma unroll
        for (int kq = 0; kq < 8; kq++) {
            float4 w4 = wr[kq];
            const int k = part * 32 + kq * 4;
            dot += s_hbar[k]     * w4.x + s_hbar[k + 1] * w4.y
                 + s_hbar[k + 2] * w4.z + s_hbar[k + 3] * w4.w;
        }
        s_cred[o][part] = dot;
    }
    __syncthreads();

    if (tid < NUM_CLASS) {
        float dot = 0.f;
#pragma unroll
        for (int p = 0; p < 8; p++) dot += s_cred[tid][p];
        float lt   = dot + cls_b[tid];
        float gate = 1.0f / (1.0f + expf(-tag_scale[0]));  // *TAG_SCALE_MAX*RAMP = *1
        out[n * NUM_CLASS + tid] = logits_base[n * NUM_CLASS + tid] + gate * lt;
    }
}

// ----------------------------------------------------------------------------
// Launch
// ----------------------------------------------------------------------------
extern "C" void kernel_launch(void* const* d_in, const int* in_sizes, int n_in,
                              void* d_out, int out_size) {
    const float* x           = (const float*)d_in[0];
    const float* feat        = (const float*)d_in[1];
    const float* logits_base = (const float*)d_in[2];
    const float* proj_w      = (const float*)d_in[3];
    const float* proj_b      = (const float*)d_in[4];
    const float* cls_w       = (const float*)d_in[5];
    const float* cls_b       = (const float*)d_in[6];
    const float* tag_scale   = (const float*)d_in[7];
    float* out = (float*)d_out;

    k_reduce<<<N_PF_BLOCKS + N_POS_BLOCKS, 320>>>(feat, x);
    k_head<<<N_BATCH, 512>>>(logits_base, proj_w, proj_b, cls_w, cls_b,
                             tag_scale, out);
}

// round 5
// speedup vs baseline: 1.1105x; 1.0683x over previous
#include <cuda_runtime.h>
#include <math.h>

// Fixed shapes
#define N_BATCH   64
#define C_IN      4
#define T_IN      300
#define V_IN      17
#define M_PERS    10
#define CF        256
#define TF        75
#define NUM_CLASS 60
#define KNN       4
#define LAMBDA_FUSE 0.1f
#define HIP_L 11

#define TV_COUNT (TF * V_IN)          // 1275
#define SLAB_F   (TV_COUNT * M_PERS)  // 12750 floats per (n,c)
#define PAIR_F   (2 * SLAB_F)         // 25500 floats per pair (float4-aligned)
#define PAIR_F4  (PAIR_F / 4)         // 6375 float4 per pair
#define STRADDLE 3187                 // float4 straddling the c boundary

#define N_PF_BLOCKS  ((N_BATCH * CF) / 2)      // 8192
#define N_POS_BLOCKS (N_BATCH * 3)             // 192
#define N_TR_BLOCKS  64                        // proj_w transpose
#define N_TOTAL_BLKS (N_PF_BLOCKS + N_POS_BLOCKS + N_TR_BLOCKS)

// Scratch (device globals: allocation-free)
__device__ float  g_pf [N_BATCH * M_PERS * CF];  // pf[n][m][c]
__device__ float  g_pos[N_BATCH * M_PERS * 3];   // pos[n][m][xyz]
__device__ float4 g_wt4[(CF / 4) * CF];          // [kq][c] = W[c][4kq..4kq+3]

// ----------------------------------------------------------------------------
// Kernel 1 (combined): blocks [0,8192) reduce feat -> g_pf.
// Blocks [8192,8384) reduce x hip rows -> g_pos.
// Blocks [8384,8448) transpose proj_w -> g_wt4 (coalesced GEMM weights).
// The small blocks hide entirely inside the DRAM-bound pf wave.
// ----------------------------------------------------------------------------
__global__ __launch_bounds__(320) void k_reduce(const float* __restrict__ feat,
                                                const float* __restrict__ x,
                                                const float* __restrict__ proj_w) {
    const int tid = threadIdx.x;
    __shared__ float sm[8][320];

    if (blockIdx.x < N_PF_BLOCKS) {
        // ---------------- pf pair reduction ----------------
        const int b  = blockIdx.x;           // n*128 + cpair
        const int n  = b >> 7;
        const int c0 = (b & 127) * 2;

        const float4* __restrict__ slab =
            reinterpret_cast<const float4*>(feat + (size_t)b * PAIR_F);

        float a0 = 0.f, a1 = 0.f, a2 = 0.f, a3 = 0.f;  // channel c0
        float d0 = 0.f, d1 = 0.f, d2 = 0.f, d3 = 0.f;  // channel c0+1
#pragma unroll
        for (int k = 0; k < 20; k++) {
            int q = tid + 320 * k;
            if (q < PAIR_F4) {
                float4 v = __ldcs(&slab[q]);           // streaming: no reuse
                if (q < STRADDLE)      { a0 += v.x; a1 += v.y; a2 += v.z; a3 += v.w; }
                else if (q > STRADDLE) { d0 += v.x; d1 += v.y; d2 += v.z; d3 += v.w; }
                else                   { a0 += v.x; a1 += v.y; d2 += v.z; d3 += v.w; }
            }
        }

        sm[0][tid] = a0; sm[1][tid] = a1; sm[2][tid] = a2; sm[3][tid] = a3;
        sm[4][tid] = d0; sm[5][tid] = d1; sm[6][tid] = d2; sm[7][tid] = d3;
        __syncthreads();

        // 20 outputs: (cc in {0,1}) x (m in 0..9). (4r + lane) % 10 == m.
        if (tid < 20) {
            const int cc = tid / 10;
            const int m  = tid % 10;
            const int r1 = m >> 2,        l1 = m & 3;
            const int r2 = (m + 10) >> 2, l2 = (m + 10) & 3;
            const float* p1 = sm[cc * 4 + l1];
            const float* p2 = sm[cc * 4 + l2];
            float acc = 0.f;
#pragma unroll
            for (int g = 0; g < 64; g++) acc += p1[g * 5 + r1] + p2[g * 5 + r2];
            g_pf[(size_t)n * (M_PERS * CF) + m * CF + (c0 + cc)] =
                acc * (1.0f / (float)TV_COUNT);
        }
    } else if (blockIdx.x < N_PF_BLOCKS + N_POS_BLOCKS) {
        // ---------------- pos reduction ----------------
        const int bb = blockIdx.x - N_PF_BLOCKS;  // n*3 + c
        const int n  = bb / 3;
        const int c  = bb % 3;
        const int j  = tid % 20;   // j<10: v=HIP_L,m=j ; j>=10: v=HIP_L+1,m=j-10
        const int tg = tid / 20;   // 0..15

        const float* base = x + ((size_t)(n * C_IN + c) * T_IN) * (V_IN * M_PERS)
                              + HIP_L * M_PERS + j;
        float s = 0.f;
#pragma unroll
        for (int k = 0; k < 19; k++) {
            int t = tg + 16 * k;
            if (t < T_IN) s += __ldcs(&base[(size_t)t * (V_IN * M_PERS)]);
        }

        sm[0][tid] = s;
        __syncthreads();

        if (tid < 20) {
            float acc = 0.f;
#pragma unroll
            for (int g = 0; g < 16; g++) acc += sm[0][g * 20 + tid];
            sm[1][tid] = acc;
        }
        __syncthreads();

        if (tid < M_PERS) {
            float v = (sm[1][tid] + sm[1][tid + 10]) * 0.5f * (1.0f / (float)T_IN);
            g_pos[n * (M_PERS * 3) + tid * 3 + c] = v;
        }
    } else {
        // ---------------- proj_w transpose: g_wt4[kq*256 + c] = W[c][4kq..]
        const int kq = blockIdx.x - (N_PF_BLOCKS + N_POS_BLOCKS);  // 0..63
        if (tid < CF) {
            const float* row = proj_w + (size_t)tid * CF + kq * 4;
            g_wt4[kq * CF + tid] =
                make_float4(row[0], row[1], row[2], row[3]);
        }
    }
}

// ----------------------------------------------------------------------------
// Kernel 2: head. One block per n, 512 threads. Coalesced weights.
// All vector-cast shared arrays are 16B-aligned (R4 crash fix).
// ----------------------------------------------------------------------------
__global__ __launch_bounds__(512) void k_head(
    const float* __restrict__ logits_base,
    const float* __restrict__ proj_b,
    const float* __restrict__ cls_w,  const float* __restrict__ cls_b,
    const float* __restrict__ tag_scale,
    float* __restrict__ out)
{
    const int n   = blockIdx.x;
    const int tid = threadIdx.x;

    __shared__ __align__(16) float s_pf[M_PERS][CF];
    __shared__ __align__(16) float s_h [M_PERS][CF];
    __shared__ __align__(16) float s_hb[2][CF];
    __shared__ __align__(16) float s_hbar[CF];
    __shared__ float s_pos[M_PERS][3];
    __shared__ float s_d [M_PERS][M_PERS];
    __shared__ float s_A [M_PERS][M_PERS];

    // ---- tiny loads ----
    {
        const float4* src = reinterpret_cast<const float4*>(
            g_pf + (size_t)n * (M_PERS * CF));
        float4* dst = reinterpret_cast<float4*>(&s_pf[0][0]);
#pragma unroll
        for (int i = tid; i < (M_PERS * CF) / 4; i += 512) dst[i] = src[i];
    }
    if (tid < M_PERS * 3) {
        s_pos[tid / 3][tid % 3] = g_pos[n * (M_PERS * 3) + tid];
    }
    __syncthreads();

    // ---- pairwise distances (only needs s_pos; runs on spare threads) ----
    if (tid >= 256 && tid < 256 + M_PERS * M_PERS) {
        const int q = tid - 256;
        const int i = q / M_PERS, j = q % M_PERS;
        float dx = s_pos[i][0] - s_pos[j][0];
        float dy = s_pos[i][1] - s_pos[j][1];
        float dz = s_pos[i][2] - s_pos[j][2];
        s_d[i][j] = sqrtf(dx * dx + dy * dy + dz * dz);
    }

    // ---- proj GEMM: tid = (half, c); 5 persons per thread.
    //      g_wt4[kq*256 + c]: lanes read contiguous 512B (coalesced).
    const int c    = tid & 255;
    const int half = tid >> 8;
    {
        float acc[5] = {0.f, 0.f, 0.f, 0.f, 0.f};
#pragma unroll 8
        for (int kq = 0; kq < CF / 4; kq++) {
            float4 w4 = g_wt4[kq * CF + c];
#pragma unroll
            for (int mm = 0; mm < 5; mm++) {
                const int m = half * 5 + mm;
                float4 p = *reinterpret_cast<const float4*>(&s_pf[m][kq * 4]);
                acc[mm] += p.x * w4.x + p.y * w4.y + p.z * w4.z + p.w * w4.w;
            }
        }
        const float bc = proj_b[c];
#pragma unroll
        for (int mm = 0; mm < 5; mm++) s_h[half * 5 + mm][c] = acc[mm] + bc;
    }
    __syncthreads();

    // ---- top-k (k=4 smallest, lowest-index tiebreak like lax.top_k) ----
    if (tid < M_PERS) {
        const int i = tid;
        float a[M_PERS];
        bool sel[M_PERS];
#pragma unroll
        for (int j = 0; j < M_PERS; j++) { a[j] = 0.f; sel[j] = false; }
#pragma unroll
        for (int s = 0; s < KNN; s++) {
            int   arg  = -1;
            float best = 3.4e38f;
#pragma unroll
            for (int j = 0; j < M_PERS; j++)
                if (!sel[j] && s_d[i][j] < best) { best = s_d[i][j]; arg = j; }
            sel[arg] = true;
            a[arg] = 1.f;
        }
        a[i] += 1.f;                      // self loop
        float rs = 0.f;
#pragma unroll
        for (int j = 0; j < M_PERS; j++) rs += a[j];
        float inv = 1.0f / (rs + 1e-6f);
#pragma unroll
        for (int j = 0; j < M_PERS; j++) s_A[i][j] = a[j] * inv;
    }
    __syncthreads();

    // ---- fuse + relu + partial mean over this half's 5 persons ----
    {
        float hb = 0.f;
#pragma unroll
        for (int mm = 0; mm < 5; mm++) {
            const int m = half * 5 + mm;
            float g = 0.f;
#pragma unroll
            for (int p = 0; p < M_PERS; p++) g += s_A[m][p] * s_h[p][c];
            float hf = s_h[m][c] + LAMBDA_FUSE * g;
            hb += fmaxf(hf, 0.f);
        }
        s_hb[half][c] = hb;
    }
    __syncthreads();

    if (tid < CF) s_hbar[tid] = (s_hb[0][tid] + s_hb[1][tid]) * (1.0f / (float)M_PERS);
    __syncthreads();

    // ---- classifier: warp-per-class, coalesced row loads + butterfly ----
    {
        const int w    = tid >> 5;     // warp 0..15
        const int lane = tid & 31;
        float4 h0 = *reinterpret_cast<const float4*>(&s_hbar[lane * 4]);
        float4 h1 = *reinterpret_cast<const float4*>(&s_hbar[128 + lane * 4]);
#pragma unroll
        for (int j = 0; j < 4; j++) {
            const int o = w + 16 * j;
            if (o < NUM_CLASS) {
                const float4* wr =
                    reinterpret_cast<const float4*>(cls_w + (size_t)o * CF);
                float4 w0 = wr[lane];
                float4 w1 = wr[lane + 32];
                float dot = w0.x * h0.x + w0.y * h0.y + w0.z * h0.z + w0.w * h0.w
                          + w1.x * h1.x + w1.y * h1.y + w1.z * h1.z + w1.w * h1.w;
#pragma unroll
                for (int s = 16; s > 0; s >>= 1)
                    dot += __shfl_xor_sync(0xFFFFFFFF, dot, s);
                if (lane == 0) {
                    float lt   = dot + cls_b[o];
                    float gate = 1.0f / (1.0f + expf(-tag_scale[0]));
                    out[n * NUM_CLASS + o] =
                        logits_base[n * NUM_CLASS + o] + gate * lt;
                }
            }
        }
    }
}

// ----------------------------------------------------------------------------
// Launch
// ----------------------------------------------------------------------------
extern "C" void kernel_launch(void* const* d_in, const int* in_sizes, int n_in,
                              void* d_out, int out_size) {
    const float* x           = (const float*)d_in[0];
    const float* feat        = (const float*)d_in[1];
    const float* logits_base = (const float*)d_in[2];
    const float* proj_w      = (const float*)d_in[3];
    const float* proj_b      = (const float*)d_in[4];
    const float* cls_w       = (const float*)d_in[5];
    const float* cls_b       = (const float*)d_in[6];
    const float* tag_scale   = (const float*)d_in[7];
    float* out = (float*)d_out;

    k_reduce<<<N_TOTAL_BLKS, 320>>>(feat, x, proj_w);
    k_head<<<N_BATCH, 512>>>(logits_base, proj_b, cls_w, cls_b,
                             tag_scale, out);
}

// round 6
// speedup vs baseline: 1.1439x; 1.0301x over previous
#include <cuda_runtime.h>
#include <math.h>

// Fixed shapes
#define N_BATCH   64
#define C_IN      4
#define T_IN      300
#define V_IN      17
#define M_PERS    10
#define CF        256
#define TF        75
#define NUM_CLASS 60
#define KNN       4
#define LAMBDA_FUSE 0.1f
#define HIP_L 11

#define TV_COUNT (TF * V_IN)          // 1275
#define SLAB_F   (TV_COUNT * M_PERS)  // 12750 floats per (n,c)
#define PAIR_F   (2 * SLAB_F)         // 25500 floats per pair (float4-aligned)
#define PAIR_F4  (PAIR_F / 4)         // 6375 float4 per pair
#define STRADDLE 3187                 // float4 straddling the c boundary

// k_reduce block layout: small latency blocks FIRST (hide in wave 1),
// then the 8192 DRAM-bound pf blocks.
#define N_POS_BLOCKS (N_BATCH * 3)             // 192
#define N_TR_BLOCKS  64                        // proj_w transpose
#define N_SMALL      (N_POS_BLOCKS + N_TR_BLOCKS)   // 256
#define N_PF_BLOCKS  ((N_BATCH * CF) / 2)      // 8192
#define N_TOTAL_BLKS (N_SMALL + N_PF_BLOCKS)

#define N_CHUNKS  4                            // k_head column chunks
#define CHUNK_C   (CF / N_CHUNKS)              // 64

// Scratch (device globals: allocation-free)
__device__ float  g_pf  [N_BATCH * M_PERS * CF];  // pf[n][m][c]
__device__ float  g_pos [N_BATCH * M_PERS * 3];   // pos[n][m][xyz]
__device__ float4 g_wt4 [(CF / 4) * CF];          // [kq][c] = W[c][4kq..4kq+3]
__device__ float  g_hbar[N_BATCH * CF];           // mean_m relu(fused h)

// ----------------------------------------------------------------------------
// Kernel 1: blocks [0,192) pos-reduce; [192,256) proj_w transpose;
// [256, 8448) feat pair reduction (DRAM-bound).
// ----------------------------------------------------------------------------
__global__ __launch_bounds__(320) void k_reduce(const float* __restrict__ feat,
                                                const float* __restrict__ x,
                                                const float* __restrict__ proj_w) {
    const int tid = threadIdx.x;
    __shared__ float sm[8][320];

    if (blockIdx.x >= N_SMALL) {
        // ---------------- pf pair reduction ----------------
        const int b  = blockIdx.x - N_SMALL;  // n*128 + cpair
        const int n  = b >> 7;
        const int c0 = (b & 127) * 2;

        const float4* __restrict__ slab =
            reinterpret_cast<const float4*>(feat + (size_t)b * PAIR_F);

        float a0 = 0.f, a1 = 0.f, a2 = 0.f, a3 = 0.f;  // channel c0
        float d0 = 0.f, d1 = 0.f, d2 = 0.f, d3 = 0.f;  // channel c0+1
#pragma unroll
        for (int k = 0; k < 20; k++) {
            int q = tid + 320 * k;
            if (q < PAIR_F4) {
                float4 v = __ldcs(&slab[q]);           // streaming: no reuse
                if (q < STRADDLE)      { a0 += v.x; a1 += v.y; a2 += v.z; a3 += v.w; }
                else if (q > STRADDLE) { d0 += v.x; d1 += v.y; d2 += v.z; d3 += v.w; }
                else                   { a0 += v.x; a1 += v.y; d2 += v.z; d3 += v.w; }
            }
        }

        sm[0][tid] = a0; sm[1][tid] = a1; sm[2][tid] = a2; sm[3][tid] = a3;
        sm[4][tid] = d0; sm[5][tid] = d1; sm[6][tid] = d2; sm[7][tid] = d3;
        __syncthreads();

        // 20 outputs: (cc in {0,1}) x (m in 0..9). (4r + lane) % 10 == m.
        if (tid < 20) {
            const int cc = tid / 10;
            const int m  = tid % 10;
            const int r1 = m >> 2,        l1 = m & 3;
            const int r2 = (m + 10) >> 2, l2 = (m + 10) & 3;
            const float* p1 = sm[cc * 4 + l1];
            const float* p2 = sm[cc * 4 + l2];
            float acc = 0.f;
#pragma unroll
            for (int g = 0; g < 64; g++) acc += p1[g * 5 + r1] + p2[g * 5 + r2];
            g_pf[(size_t)n * (M_PERS * CF) + m * CF + (c0 + cc)] =
                acc * (1.0f / (float)TV_COUNT);
        }
    } else if (blockIdx.x < N_POS_BLOCKS) {
        // ---------------- pos reduction ----------------
        const int bb = blockIdx.x;  // n*3 + c
        const int n  = bb / 3;
        const int c  = bb % 3;
        const int j  = tid % 20;   // j<10: v=HIP_L,m=j ; j>=10: v=HIP_L+1,m=j-10
        const int tg = tid / 20;   // 0..15

        const float* base = x + ((size_t)(n * C_IN + c) * T_IN) * (V_IN * M_PERS)
                              + HIP_L * M_PERS + j;
        float s = 0.f;
#pragma unroll
        for (int k = 0; k < 19; k++) {
            int t = tg + 16 * k;
            if (t < T_IN) s += __ldcs(&base[(size_t)t * (V_IN * M_PERS)]);
        }

        sm[0][tid] = s;
        __syncthreads();

        if (tid < 20) {
            float acc = 0.f;
#pragma unroll
            for (int g = 0; g < 16; g++) acc += sm[0][g * 20 + tid];
            sm[1][tid] = acc;
        }
        __syncthreads();

        if (tid < M_PERS) {
            float v = (sm[1][tid] + sm[1][tid + 10]) * 0.5f * (1.0f / (float)T_IN);
            g_pos[n * (M_PERS * 3) + tid * 3 + c] = v;
        }
    } else {
        // ---------------- proj_w transpose: g_wt4[kq*256 + c] = W[c][4kq..]
        const int kq = blockIdx.x - N_POS_BLOCKS;  // 0..63
        if (tid < CF) {
            const float* row = proj_w + (size_t)tid * CF + kq * 4;
            g_wt4[kq * CF + tid] = make_float4(row[0], row[1], row[2], row[3]);
        }
    }
}

// ----------------------------------------------------------------------------
// Kernel 2: head chunks. Grid = 64 n x 4 column-chunks, 640 threads.
// Thread = (m, c_local). Emits hbar slice -> g_hbar.
// ----------------------------------------------------------------------------
__global__ __launch_bounds__(640) void k_head(const float* __restrict__ proj_b)
{
    const int n     = blockIdx.x >> 2;
    const int chunk = blockIdx.x & 3;
    const int tid   = threadIdx.x;
    const int m     = tid >> 6;          // 0..9
    const int cl    = tid & 63;          // 0..63
    const int c     = chunk * CHUNK_C + cl;

    __shared__ __align__(16) float s_pf[M_PERS][CF];
    __shared__ float s_h  [M_PERS][CHUNK_C];
    __shared__ float s_hf [M_PERS][CHUNK_C];
    __shared__ float s_pos[M_PERS][3];
    __shared__ float s_d  [M_PERS][M_PERS];
    __shared__ float s_A  [M_PERS][M_PERS];

    // ---- loads: exactly 640 float4 for s_pf, one per thread ----
    {
        const float4* src = reinterpret_cast<const float4*>(
            g_pf + (size_t)n * (M_PERS * CF));
        reinterpret_cast<float4*>(&s_pf[0][0])[tid] = src[tid];
    }
    if (tid < M_PERS * 3) s_pos[tid / 3][tid % 3] = g_pos[n * (M_PERS * 3) + tid];
    __syncthreads();

    // ---- pairwise distances (100 threads, needs only s_pos) ----
    if (tid < M_PERS * M_PERS) {
        const int i = tid / M_PERS, j = tid % M_PERS;
        float dx = s_pos[i][0] - s_pos[j][0];
        float dy = s_pos[i][1] - s_pos[j][1];
        float dz = s_pos[i][2] - s_pos[j][2];
        s_d[i][j] = sqrtf(dx * dx + dy * dy + dz * dz);
    }

    // ---- GEMM: h[m][c] = dot(pf[m][:], W[c][:]) + b[c] ----
    {
        float acc = 0.f;
#pragma unroll 8
        for (int kq = 0; kq < CF / 4; kq++) {
            float4 w4 = g_wt4[kq * CF + c];                       // coalesced LDG
            float4 p  = *reinterpret_cast<const float4*>(&s_pf[m][kq * 4]); // bcast
            acc += p.x * w4.x + p.y * w4.y + p.z * w4.z + p.w * w4.w;
        }
        s_h[m][cl] = acc + proj_b[c];
    }
    __syncthreads();

    // ---- top-k adjacency (k=4 smallest, lowest-index tiebreak) ----
    if (tid < M_PERS) {
        const int i = tid;
        float a[M_PERS];
        bool sel[M_PERS];
#pragma unroll
        for (int j = 0; j < M_PERS; j++) { a[j] = 0.f; sel[j] = false; }
#pragma unroll
        for (int s = 0; s < KNN; s++) {
            int   arg  = -1;
            float best = 3.4e38f;
#pragma unroll
            for (int j = 0; j < M_PERS; j++)
                if (!sel[j] && s_d[i][j] < best) { best = s_d[i][j]; arg = j; }
            sel[arg] = true;
            a[arg] = 1.f;
        }
        a[i] += 1.f;                      // self loop
        float rs = 0.f;
#pragma unroll
        for (int j = 0; j < M_PERS; j++) rs += a[j];
        float inv = 1.0f / (rs + 1e-6f);
#pragma unroll
        for (int j = 0; j < M_PERS; j++) s_A[i][j] = a[j] * inv;
    }
    __syncthreads();

    // ---- fuse + relu ----
    {
        float g = 0.f;
#pragma unroll
        for (int p = 0; p < M_PERS; p++) g += s_A[m][p] * s_h[p][cl];
        s_hf[m][cl] = fmaxf(s_h[m][cl] + LAMBDA_FUSE * g, 0.f);
    }
    __syncthreads();

    // ---- mean over persons -> hbar slice ----
    if (tid < CHUNK_C) {
        float hb = 0.f;
#pragma unroll
        for (int mm = 0; mm < M_PERS; mm++) hb += s_hf[mm][tid];
        g_hbar[n * CF + chunk * CHUNK_C + tid] = hb * (1.0f / (float)M_PERS);
    }
}

// ----------------------------------------------------------------------------
// Kernel 3: classifier. Grid = 64, 512 threads, warp-per-class + butterfly.
// ----------------------------------------------------------------------------
__global__ __launch_bounds__(512) void k_cls(
    const float* __restrict__ logits_base,
    const float* __restrict__ cls_w, const float* __restrict__ cls_b,
    const float* __restrict__ tag_scale,
    float* __restrict__ out)
{
    const int n   = blockIdx.x;
    const int tid = threadIdx.x;

    __shared__ __align__(16) float s_hbar[CF];
    if (tid < CF / 4) {
        reinterpret_cast<float4*>(s_hbar)[tid] =
            reinterpret_cast<const float4*>(g_hbar + n * CF)[tid];
    }
    __syncthreads();

    const int w    = tid >> 5;     // warp 0..15
    const int lane = tid & 31;
    float4 h0 = *reinterpret_cast<const float4*>(&s_hbar[lane * 4]);
    float4 h1 = *reinterpret_cast<const float4*>(&s_hbar[128 + lane * 4]);
#pragma unroll
    for (int j = 0; j < 4; j++) {
        const int o = w + 16 * j;
        if (o < NUM_CLASS) {
            const float4* wr = reinterpret_cast<const float4*>(cls_w + (size_t)o * CF);
            float4 w0 = wr[lane];
            float4 w1 = wr[lane + 32];
            float dot = w0.x * h0.x + w0.y * h0.y + w0.z * h0.z + w0.w * h0.w
                      + w1.x * h1.x + w1.y * h1.y + w1.z * h1.z + w1.w * h1.w;
#pragma unroll
            for (int s = 16; s > 0; s >>= 1)
                dot += __shfl_xor_sync(0xFFFFFFFF, dot, s);
            if (lane == 0) {
                float lt   = dot + cls_b[o];
                float gate = 1.0f / (1.0f + expf(-tag_scale[0]));
                out[n * NUM_CLASS + o] = logits_base[n * NUM_CLASS + o] + gate * lt;
            }
        }
    }
}

// ----------------------------------------------------------------------------
// Launch
// ----------------------------------------------------------------------------
extern "C" void kernel_launch(void* const* d_in, const int* in_sizes, int n_in,
                              void* d_out, int out_size) {
    const float* x           = (const float*)d_in[0];
    const float* feat        = (const float*)d_in[1];
    const float* logits_base = (const float*)d_in[2];
    const float* proj_w      = (const float*)d_in[3];
    const float* proj_b      = (const float*)d_in[4];
    const float* cls_w       = (const float*)d_in[5];
    const float* cls_b       = (const float*)d_in[6];
    const float* tag_scale   = (const float*)d_in[7];
    float* out = (float*)d_out;

    k_reduce<<<N_TOTAL_BLKS, 320>>>(feat, x, proj_w);
    k_head<<<N_BATCH * N_CHUNKS, 640>>>(proj_b);
    k_cls<<<N_BATCH, 512>>>(logits_base, cls_w, cls_b, tag_scale, out);
}

// round 7
// speedup vs baseline: 1.1612x; 1.0152x over previous
#include <cuda_runtime.h>
#include <math.h>

// Fixed shapes
#define N_BATCH   64
#define C_IN      4
#define T_IN      300
#define V_IN      17
#define M_PERS    10
#define CF        256
#define TF        75
#define NUM_CLASS 60
#define KNN       4
#define LAMBDA_FUSE 0.1f
#define HIP_L 11

#define TV_COUNT (TF * V_IN)          // 1275
#define SLAB_F   (TV_COUNT * M_PERS)  // 12750 floats per (n,c)
#define PAIR_F   (2 * SLAB_F)         // 25500 floats per pair (float4-aligned)
#define PAIR_F4  (PAIR_F / 4)         // 6375 float4 per pair
#define STRADDLE 3187                 // float4 straddling the c boundary

// Block layout: DRAM-bound pf blocks FIRST, small latency blocks LAST
// (they draft behind the DRAM wave for free; putting them in wave 1
// cost ~17us in R6).
#define N_PF_BLOCKS  ((N_BATCH * CF) / 2)      // 8192
#define N_POS_BLOCKS (N_BATCH * 3)             // 192
#define N_TR_BLOCKS  64                        // proj_w transpose
#define N_TOTAL_BLKS (N_PF_BLOCKS + N_POS_BLOCKS + N_TR_BLOCKS)

#define N_CHUNKS  4                            // k_head column chunks
#define CHUNK_C   (CF / N_CHUNKS)              // 64

// Scratch (device globals: allocation-free)
__device__ float  g_pf  [N_BATCH * M_PERS * CF];  // pf[n][m][c]
__device__ float  g_pos [N_BATCH * M_PERS * 3];   // pos[n][m][xyz]
__device__ float4 g_wt4 [(CF / 4) * CF];          // [kq][c] = W[c][4kq..4kq+3]
__device__ float  g_hbar[N_BATCH * CF];           // mean_m relu(fused h)

// ----------------------------------------------------------------------------
// Kernel 1: blocks [0,8192) feat pair reduction (DRAM-bound);
// [8192,8384) pos-reduce; [8384,8448) proj_w transpose.
// ----------------------------------------------------------------------------
__global__ __launch_bounds__(320) void k_reduce(const float* __restrict__ feat,
                                                const float* __restrict__ x,
                                                const float* __restrict__ proj_w) {
    const int tid = threadIdx.x;
    __shared__ float sm[8][320];

    if (blockIdx.x < N_PF_BLOCKS) {
        // ---------------- pf pair reduction ----------------
        const int b  = blockIdx.x;           // n*128 + cpair
        const int n  = b >> 7;
        const int c0 = (b & 127) * 2;

        const float4* __restrict__ slab =
            reinterpret_cast<const float4*>(feat + (size_t)b * PAIR_F);

        float a0 = 0.f, a1 = 0.f, a2 = 0.f, a3 = 0.f;  // channel c0
        float d0 = 0.f, d1 = 0.f, d2 = 0.f, d3 = 0.f;  // channel c0+1
#pragma unroll
        for (int k = 0; k < 20; k++) {
            int q = tid + 320 * k;
            if (q < PAIR_F4) {
                float4 v = __ldcs(&slab[q]);           // streaming: no reuse
                if (q < STRADDLE)      { a0 += v.x; a1 += v.y; a2 += v.z; a3 += v.w; }
                else if (q > STRADDLE) { d0 += v.x; d1 += v.y; d2 += v.z; d3 += v.w; }
                else                   { a0 += v.x; a1 += v.y; d2 += v.z; d3 += v.w; }
            }
        }

        sm[0][tid] = a0; sm[1][tid] = a1; sm[2][tid] = a2; sm[3][tid] = a3;
        sm[4][tid] = d0; sm[5][tid] = d1; sm[6][tid] = d2; sm[7][tid] = d3;
        __syncthreads();

        // 20 outputs: (cc in {0,1}) x (m in 0..9). (4r + lane) % 10 == m.
        if (tid < 20) {
            const int cc = tid / 10;
            const int m  = tid % 10;
            const int r1 = m >> 2,        l1 = m & 3;
            const int r2 = (m + 10) >> 2, l2 = (m + 10) & 3;
            const float* p1 = sm[cc * 4 + l1];
            const float* p2 = sm[cc * 4 + l2];
            float acc = 0.f;
#pragma unroll
            for (int g = 0; g < 64; g++) acc += p1[g * 5 + r1] + p2[g * 5 + r2];
            g_pf[(size_t)n * (M_PERS * CF) + m * CF + (c0 + cc)] =
                acc * (1.0f / (float)TV_COUNT);
        }
    } else if (blockIdx.x < N_PF_BLOCKS + N_POS_BLOCKS) {
        // ---------------- pos reduction ----------------
        const int bb = blockIdx.x - N_PF_BLOCKS;  // n*3 + c
        const int n  = bb / 3;
        const int c  = bb % 3;
        const int j  = tid % 20;   // j<10: v=HIP_L,m=j ; j>=10: v=HIP_L+1,m=j-10
        const int tg = tid / 20;   // 0..15

        const float* base = x + ((size_t)(n * C_IN + c) * T_IN) * (V_IN * M_PERS)
                              + HIP_L * M_PERS + j;
        float s = 0.f;
#pragma unroll
        for (int k = 0; k < 19; k++) {
            int t = tg + 16 * k;
            if (t < T_IN) s += __ldcs(&base[(size_t)t * (V_IN * M_PERS)]);
        }

        sm[0][tid] = s;
        __syncthreads();

        if (tid < 20) {
            float acc = 0.f;
#pragma unroll
            for (int g = 0; g < 16; g++) acc += sm[0][g * 20 + tid];
            sm[1][tid] = acc;
        }
        __syncthreads();

        if (tid < M_PERS) {
            float v = (sm[1][tid] + sm[1][tid + 10]) * 0.5f * (1.0f / (float)T_IN);
            g_pos[n * (M_PERS * 3) + tid * 3 + c] = v;
        }
    } else {
        // ---------------- proj_w transpose: g_wt4[kq*256 + c] = W[c][4kq..]
        const int kq = blockIdx.x - (N_PF_BLOCKS + N_POS_BLOCKS);  // 0..63
        if (tid < CF) {
            const float* row = proj_w + (size_t)tid * CF + kq * 4;
            g_wt4[kq * CF + tid] = make_float4(row[0], row[1], row[2], row[3]);
        }
    }
}

// ----------------------------------------------------------------------------
// Kernel 2: head chunks. Grid = 64 n x 4 column-chunks, 640 threads.
// Thread = (m, c_local). Emits hbar slice -> g_hbar.
// ----------------------------------------------------------------------------
__global__ __launch_bounds__(640) void k_head(const float* __restrict__ proj_b)
{
    const int n     = blockIdx.x >> 2;
    const int chunk = blockIdx.x & 3;
    const int tid   = threadIdx.x;
    const int m     = tid >> 6;          // 0..9
    const int cl    = tid & 63;          // 0..63
    const int c     = chunk * CHUNK_C + cl;

    __shared__ __align__(16) float s_pf[M_PERS][CF];
    __shared__ float s_h  [M_PERS][CHUNK_C];
    __shared__ float s_hf [M_PERS][CHUNK_C];
    __shared__ float s_pos[M_PERS][3];
    __shared__ float s_d  [M_PERS][M_PERS];
    __shared__ float s_A  [M_PERS][M_PERS];

    // ---- loads: exactly 640 float4 for s_pf, one per thread ----
    {
        const float4* src = reinterpret_cast<const float4*>(
            g_pf + (size_t)n * (M_PERS * CF));
        reinterpret_cast<float4*>(&s_pf[0][0])[tid] = src[tid];
    }
    if (tid < M_PERS * 3) s_pos[tid / 3][tid % 3] = g_pos[n * (M_PERS * 3) + tid];
    __syncthreads();

    // ---- pairwise distances (100 threads, needs only s_pos) ----
    if (tid < M_PERS * M_PERS) {
        const int i = tid / M_PERS, j = tid % M_PERS;
        float dx = s_pos[i][0] - s_pos[j][0];
        float dy = s_pos[i][1] - s_pos[j][1];
        float dz = s_pos[i][2] - s_pos[j][2];
        s_d[i][j] = sqrtf(dx * dx + dy * dy + dz * dz);
    }

    // ---- GEMM: h[m][c] = dot(pf[m][:], W[c][:]) + b[c] ----
    {
        float acc = 0.f;
#pragma unroll 8
        for (int kq = 0; kq < CF / 4; kq++) {
            float4 w4 = g_wt4[kq * CF + c];                       // coalesced LDG
            float4 p  = *reinterpret_cast<const float4*>(&s_pf[m][kq * 4]); // bcast
            acc += p.x * w4.x + p.y * w4.y + p.z * w4.z + p.w * w4.w;
        }
        s_h[m][cl] = acc + proj_b[c];
    }
    __syncthreads();

    // ---- top-k adjacency (k=4 smallest, lowest-index tiebreak) ----
    if (tid < M_PERS) {
        const int i = tid;
        float a[M_PERS];
        bool sel[M_PERS];
#pragma unroll
        for (int j = 0; j < M_PERS; j++) { a[j] = 0.f; sel[j] = false; }
#pragma unroll
        for (int s = 0; s < KNN; s++) {
            int   arg  = -1;
            float best = 3.4e38f;
#pragma unroll
            for (int j = 0; j < M_PERS; j++)
                if (!sel[j] && s_d[i][j] < best) { best = s_d[i][j]; arg = j; }
            sel[arg] = true;
            a[arg] = 1.f;
        }
        a[i] += 1.f;                      // self loop
        float rs = 0.f;
#pragma unroll
        for (int j = 0; j < M_PERS; j++) rs += a[j];
        float inv = 1.0f / (rs + 1e-6f);
#pragma unroll
        for (int j = 0; j < M_PERS; j++) s_A[i][j] = a[j] * inv;
    }
    __syncthreads();

    // ---- fuse + relu ----
    {
        float g = 0.f;
#pragma unroll
        for (int p = 0; p < M_PERS; p++) g += s_A[m][p] * s_h[p][cl];
        s_hf[m][cl] = fmaxf(s_h[m][cl] + LAMBDA_FUSE * g, 0.f);
    }
    __syncthreads();

    // ---- mean over persons -> hbar slice ----
    if (tid < CHUNK_C) {
        float hb = 0.f;
#pragma unroll
        for (int mm = 0; mm < M_PERS; mm++) hb += s_hf[mm][tid];
        g_hbar[n * CF + chunk * CHUNK_C + tid] = hb * (1.0f / (float)M_PERS);
    }
}

// ----------------------------------------------------------------------------
// Kernel 3: classifier. Grid = 64, 512 threads, warp-per-class + butterfly.
// ----------------------------------------------------------------------------
__global__ __launch_bounds__(512) void k_cls(
    const float* __restrict__ logits_base,
    const float* __restrict__ cls_w, const float* __restrict__ cls_b,
    const float* __restrict__ tag_scale,
    float* __restrict__ out)
{
    const int n   = blockIdx.x;
    const int tid = threadIdx.x;

    __shared__ __align__(16) float s_hbar[CF];
    if (tid < CF / 4) {
        reinterpret_cast<float4*>(s_hbar)[tid] =
            reinterpret_cast<const float4*>(g_hbar + n * CF)[tid];
    }
    __syncthreads();

    const int w    = tid >> 5;     // warp 0..15
    const int lane = tid & 31;
    float4 h0 = *reinterpret_cast<const float4*>(&s_hbar[lane * 4]);
    float4 h1 = *reinterpret_cast<const float4*>(&s_hbar[128 + lane * 4]);
#pragma unroll
    for (int j = 0; j < 4; j++) {
        const int o = w + 16 * j;
        if (o < NUM_CLASS) {
            const float4* wr = reinterpret_cast<const float4*>(cls_w + (size_t)o * CF);
            float4 w0 = wr[lane];
            float4 w1 = wr[lane + 32];
            float dot = w0.x * h0.x + w0.y * h0.y + w0.z * h0.z + w0.w * h0.w
                      + w1.x * h1.x + w1.y * h1.y + w1.z * h1.z + w1.w * h1.w;
#pragma unroll
            for (int s = 16; s > 0; s >>= 1)
                dot += __shfl_xor_sync(0xFFFFFFFF, dot, s);
            if (lane == 0) {
                float lt   = dot + cls_b[o];
                float gate = 1.0f / (1.0f + expf(-tag_scale[0]));
                out[n * NUM_CLASS + o] = logits_base[n * NUM_CLASS + o] + gate * lt;
            }
        }
    }
}

// ----------------------------------------------------------------------------
// Launch
// ----------------------------------------------------------------------------
extern "C" void kernel_launch(void* const* d_in, const int* in_sizes, int n_in,
                              void* d_out, int out_size) {
    const float* x           = (const float*)d_in[0];
    const float* feat        = (const float*)d_in[1];
    const float* logits_base = (const float*)d_in[2];
    const float* proj_w      = (const float*)d_in[3];
    const float* proj_b      = (const float*)d_in[4];
    const float* cls_w       = (const float*)d_in[5];
    const float* cls_b       = (const float*)d_in[6];
    const float* tag_scale   = (const float*)d_in[7];
    float* out = (float*)d_out;

    k_reduce<<<N_TOTAL_BLKS, 320>>>(feat, x, proj_w);
    k_head<<<N_BATCH * N_CHUNKS, 640>>>(proj_b);
    k_cls<<<N_BATCH, 512>>>(logits_base, cls_w, cls_b, tag_scale, out);
}